// round 1
// baseline (speedup 1.0000x reference)
#include <cuda_runtime.h>

#define B_ 8
#define C_ 32
#define F_ 32
#define Q_ 9
#define H_ 32
#define W_ 32

// Coeff entry layout per (q,c): [a0 a1 a2 a3 | a4 a5 b1 b2 | b3 b4 pad pad]  (12 floats, 48B, 16B aligned)
// smem: coeffs 9*32*12*4 = 13824B, plane 18*34*4 = 2448B  -> ~16.3KB/CTA

__global__ __launch_bounds__(128) void kaconv_kernel(
    const float* __restrict__ x,
    const float* __restrict__ nums,
    const float* __restrict__ denoms,
    float* __restrict__ out)
{
    __shared__ float cs[Q_ * C_ * 12];
    __shared__ float splane[18 * 34];

    const int tid  = threadIdx.x;
    const int blk  = blockIdx.x;
    const int half = blk & 1;          // which 16-row slab
    const int bf   = blk >> 1;
    const int f    = bf & (F_ - 1);
    const int b    = bf >> 5;
    const int row0 = half * 16;

    // ---- stage coefficients for this f (broadcast-shared by whole CTA) ----
    for (int e = tid; e < Q_ * C_; e += 128) {
        const int gbase = f * Q_ * C_ + e;            // ((f*Q+q)*C + c)
        const float* np = nums   + gbase * 6;
        const float* dp = denoms + gbase * 4;
        float* o = cs + e * 12;
        o[0] = np[0]; o[1] = np[1]; o[2] = np[2]; o[3] = np[3];
        o[4] = np[4]; o[5] = np[5];
        o[6] = dp[0]; o[7] = dp[1]; o[8] = dp[2]; o[9] = dp[3];
        o[10] = 0.f;  o[11] = 0.f;
    }

    const int lane_r = tid >> 5;   // 0..3 (warp -> row within 4-row group)
    const int col    = tid & 31;   // 0..31 (lane -> x column, conflict-free LDS)

    float acc[4] = {0.f, 0.f, 0.f, 0.f};

    const float* xb = x + (size_t)(b * C_) * (H_ * W_);

    for (int c = 0; c < C_; ++c) {
        __syncthreads();   // coeffs visible (1st iter) / previous plane fully consumed
        // ---- stage zero-padded plane rows [row0-1 .. row0+16], cols [-1..32] ----
        const float* xc = xb + c * (H_ * W_);
        for (int i = tid; i < 18 * 34; i += 128) {
            const int r  = i / 34;          // 0..17
            const int cc = i - r * 34;      // 0..33
            const int gr = row0 - 1 + r;
            const int gc = cc - 1;
            float v = 0.f;
            if (gr >= 0 && gr < H_ && gc >= 0 && gc < W_)
                v = xc[gr * W_ + gc];
            splane[i] = v;
        }
        __syncthreads();

        #pragma unroll
        for (int q = 0; q < Q_; ++q) {
            const int dy = q / 3;
            const int dx = q - dy * 3;
            const float4* cp = (const float4*)(cs + (q * C_ + c) * 12);
            const float4 A = cp[0];   // a0 a1 a2 a3
            const float4 Bv = cp[1];  // a4 a5 b1 b2
            const float4 Cv = cp[2];  // b3 b4 -- --

            const int base = (lane_r + dy) * 34 + col + dx;
            #pragma unroll
            for (int k = 0; k < 4; ++k) {
                const float w = splane[base + k * (4 * 34)];
                // numerator: a0 + a1 w + ... + a5 w^5 (Horner)
                float num = fmaf(Bv.y, w, Bv.x);   // a5*w + a4
                num = fmaf(num, w, A.w);
                num = fmaf(num, w, A.z);
                num = fmaf(num, w, A.y);
                num = fmaf(num, w, A.x);
                // denominator poly: b1 w + b2 w^2 + b3 w^3 + b4 w^4
                float d = fmaf(Cv.y, w, Cv.x);     // b4*w + b3
                d = fmaf(d, w, Bv.w);
                d = fmaf(d, w, Bv.z);
                d = d * w;
                const float den = 1.0f + fabsf(d);
                acc[k] += __fdividef(num, den);
            }
        }
    }

    // ---- write: pixel k -> (y = row0 + 4k + lane_r, x = col) ----
    float* ob = out + ((size_t)(b * F_ + f)) * (H_ * W_);
    #pragma unroll
    for (int k = 0; k < 4; ++k) {
        const int y = row0 + 4 * k + lane_r;
        ob[y * W_ + col] = acc[k];
    }
}

extern "C" void kernel_launch(void* const* d_in, const int* in_sizes, int n_in,
                              void* d_out, int out_size)
{
    const float* x      = (const float*)d_in[0];
    const float* nums   = (const float*)d_in[1];
    const float* denoms = (const float*)d_in[2];
    float* out          = (float*)d_out;
    (void)in_sizes; (void)n_in; (void)out_size;

    // grid = B*F*2 halves = 512 CTAs, 128 threads, 4 pixels/thread
    kaconv_kernel<<<B_ * F_ * 2, 128>>>(x, nums, denoms, out);
}

// round 2
// speedup vs baseline: 1.0389x; 1.0389x over previous
#include <cuda_runtime.h>

#define B_ 8
#define C_ 32
#define F_ 32
#define Q_ 9
#define H_ 32
#define W_ 32

// ---- f32x2 packed helpers (sm_103a) ----
typedef unsigned long long u64;

__device__ __forceinline__ u64 pack2(float lo, float hi) {
    u64 r; asm("mov.b64 %0, {%1, %2};" : "=l"(r) : "f"(lo), "f"(hi)); return r;
}
__device__ __forceinline__ void unpack2(u64 v, float& lo, float& hi) {
    asm("mov.b64 {%0, %1}, %2;" : "=f"(lo), "=f"(hi) : "l"(v));
}
__device__ __forceinline__ u64 fma2(u64 a, u64 b, u64 c) {
    u64 d; asm("fma.rn.f32x2 %0, %1, %2, %3;" : "=l"(d) : "l"(a), "l"(b), "l"(c)); return d;
}
__device__ __forceinline__ u64 mul2(u64 a, u64 b) {
    u64 d; asm("mul.rn.f32x2 %0, %1, %2;" : "=l"(d) : "l"(a), "l"(b)); return d;
}
__device__ __forceinline__ u64 add2(u64 a, u64 b) {
    u64 d; asm("add.rn.f32x2 %0, %1, %2;" : "=l"(d) : "l"(a), "l"(b)); return d;
}
__device__ __forceinline__ float rcpf(float x) {
    float r; asm("rcp.approx.ftz.f32 %0, %1;" : "=f"(r) : "f"(x)); return r;
}

// smem: duplicated coeffs 9*32*10 u64 = 23040B, plane 10*34*4 = 1360B -> ~24.5KB/CTA
__global__ __launch_bounds__(128) void kaconv_kernel(
    const float* __restrict__ x,
    const float* __restrict__ nums,
    const float* __restrict__ denoms,
    float* __restrict__ out)
{
    __shared__ u64   cs2[Q_ * C_ * 10];   // per (q,c): a0a1 a2a3 a4a5 b1b2 b3b4 (each as {v,v})
    __shared__ float splane[10 * 34];     // 8-row slab + halo

    const int tid  = threadIdx.x;
    const int blk  = blockIdx.x;
    const int slab = blk & 3;             // 4 slabs of 8 rows
    const int bf   = blk >> 2;
    const int f    = bf & (F_ - 1);
    const int b    = bf >> 5;
    const int row0 = slab * 8;

    // ---- stage duplicated coefficients for this f ----
    for (int e = tid; e < Q_ * C_; e += 128) {
        const int gbase = f * Q_ * C_ + e;
        const float* np = nums   + gbase * 6;
        const float* dp = denoms + gbase * 4;
        u64* o = cs2 + e * 10;
        o[0] = pack2(np[0], np[0]);
        o[1] = pack2(np[1], np[1]);
        o[2] = pack2(np[2], np[2]);
        o[3] = pack2(np[3], np[3]);
        o[4] = pack2(np[4], np[4]);
        o[5] = pack2(np[5], np[5]);
        o[6] = pack2(dp[0], dp[0]);
        o[7] = pack2(dp[1], dp[1]);
        o[8] = pack2(dp[2], dp[2]);
        o[9] = pack2(dp[3], dp[3]);
    }

    const int lane_r = tid >> 5;   // 0..3 -> output rows row0+lane_r (lo), row0+lane_r+4 (hi)
    const int col    = tid & 31;   // conflict-free LDS column

    const u64 ONE2 = pack2(1.0f, 1.0f);
    u64 acc = pack2(0.f, 0.f);

    const float* xb = x + (size_t)(b * C_) * (H_ * W_);

    for (int c = 0; c < C_; ++c) {
        __syncthreads();   // coeffs visible (1st iter) / previous plane consumed
        // ---- stage zero-padded plane rows [row0-1 .. row0+8], cols [-1..32] ----
        const float* xc = xb + c * (H_ * W_);
        for (int i = tid; i < 10 * 34; i += 128) {
            const int r  = i / 34;
            const int cc = i - r * 34;
            const int gr = row0 - 1 + r;
            const int gc = cc - 1;
            float v = 0.f;
            if (gr >= 0 && gr < H_ && gc >= 0 && gc < W_)
                v = xc[gr * W_ + gc];
            splane[i] = v;
        }
        __syncthreads();

        #pragma unroll
        for (int q = 0; q < Q_; ++q) {
            const int dy = q / 3;
            const int dx = q - dy * 3;
            // 5x LDS.128 broadcast of duplicated coeff pairs
            const ulonglong2* cp = (const ulonglong2*)(cs2 + (q * C_ + c) * 10);
            const ulonglong2 p01 = cp[0];   // a0, a1
            const ulonglong2 p23 = cp[1];   // a2, a3
            const ulonglong2 p45 = cp[2];   // a4, a5
            const ulonglong2 d12 = cp[3];   // b1, b2
            const ulonglong2 d34 = cp[4];   // b3, b4

            const int base = (lane_r + dy) * 34 + col + dx;
            const float w_lo = splane[base];
            const float w_hi = splane[base + 4 * 34];
            const u64 w2 = pack2(w_lo, w_hi);

            // numerator Horner: ((((a5*w+a4)*w+a3)*w+a2)*w+a1)*w+a0
            u64 num = fma2(p45.y, w2, p45.x);
            num = fma2(num, w2, p23.y);
            num = fma2(num, w2, p23.x);
            num = fma2(num, w2, p01.y);
            num = fma2(num, w2, p01.x);
            // denominator poly: w*(b1 + w*(b2 + w*(b3 + w*b4)))
            u64 d = fma2(d34.y, w2, d34.x);
            d = fma2(d, w2, d12.y);
            d = fma2(d, w2, d12.x);
            d = mul2(d, w2);
            d &= 0x7FFFFFFF7FFFFFFFULL;          // |d| per lane (ALU pipe)
            const u64 den = add2(ONE2, d);
            float den_lo, den_hi;
            unpack2(den, den_lo, den_hi);        // free: register pair halves
            const u64 r2 = pack2(rcpf(den_lo), rcpf(den_hi));
            acc = fma2(num, r2, acc);
        }
    }

    // ---- write 2 pixels ----
    float a_lo, a_hi;
    unpack2(acc, a_lo, a_hi);
    float* ob = out + ((size_t)(b * F_ + f)) * (H_ * W_);
    ob[(row0 + lane_r) * W_ + col]     = a_lo;
    ob[(row0 + lane_r + 4) * W_ + col] = a_hi;
}

extern "C" void kernel_launch(void* const* d_in, const int* in_sizes, int n_in,
                              void* d_out, int out_size)
{
    const float* x      = (const float*)d_in[0];
    const float* nums   = (const float*)d_in[1];
    const float* denoms = (const float*)d_in[2];
    float* out          = (float*)d_out;
    (void)in_sizes; (void)n_in; (void)out_size;

    kaconv_kernel<<<B_ * F_ * 4, 128>>>(x, nums, denoms, out);
}